// round 1
// baseline (speedup 1.0000x reference)
#include <cuda_runtime.h>

// Problem constants
#define BB   2048
#define NAG  8
#define ACT  16
#define HD   32
#define HIDN 64
// DQ = (HD+ACT)*NAG = 384, per-agent feature stride = 48

// Scratch (allowed: __device__ global arrays)
__device__ float g_u[BB * NAG * HIDN];        // u[b,g,n] = base(b)+b1 - corr(b,g)   (4 MB)
__device__ float g_w1aT[HIDN * NAG * ACT];    // w1aT[k*128 + (g*16+a)] = W1[(g*48+32+a)*64 + k]

// ---------------------------------------------------------------------------
// Kernel 1: layer-1 factorization.
// Thread = (b, n): computes base(b)[n] and per-agent action contributions,
// writes u[b,g,n] for all 8 agents. CTA 0 additionally writes the transposed
// W1 action-row block used by kernel 2.
// ---------------------------------------------------------------------------
__global__ void __launch_bounds__(256) prep_kernel(
    const float* __restrict__ hidden,   // [B, 8, 32]
    const float* __restrict__ actions,  // [B, 8, 16]
    const float* __restrict__ w1,       // [384, 64]
    const float* __restrict__ b1)       // [64]
{
    const int tid = threadIdx.x;
    const int b = blockIdx.x * 4 + (tid >> 6);
    const int n = tid & 63;

    if (blockIdx.x == 0) {
        // Transpose the 128 action rows of W1: g_w1aT[k*128 + ga] = w1[(g*48+32+a)*64 + k]
        for (int e = tid; e < HIDN * 128; e += 256) {
            const int k  = e >> 7;
            const int ga = e & 127;
            const int g  = ga >> 4;
            const int a  = ga & 15;
            g_w1aT[e] = w1[(g * 48 + 32 + a) * 64 + k];
        }
    }

    const float* hb = hidden  + b * (NAG * HD);
    const float* ab = actions + b * (NAG * ACT);

    // Hidden-feature part of base(b)[n] (+ bias)
    float base = b1[n];
    #pragma unroll 4
    for (int j = 0; j < NAG; ++j) {
        #pragma unroll
        for (int i = 0; i < HD; ++i)
            base = fmaf(hb[j * HD + i], w1[(j * 48 + i) * 64 + n], base);
    }

    // Per-agent true-action contributions
    float asum[NAG];
    float tot = 0.f;
    #pragma unroll
    for (int g = 0; g < NAG; ++g) {
        float s = 0.f;
        #pragma unroll
        for (int a = 0; a < ACT; ++a)
            s = fmaf(ab[g * ACT + a], w1[(g * 48 + 32 + a) * 64 + n], s);
        asum[g] = s;
        tot += s;
    }

    // u[b,g,n] = base + sum_j act_j - act_g   (agent g's action removed)
    #pragma unroll
    for (int g = 0; g < NAG; ++g)
        g_u[(b * NAG + g) * HIDN + n] = base + tot - asum[g];
}

// ---------------------------------------------------------------------------
// Kernel 2: fused layers 2+3.
// 1 CTA per batch element b, 128 threads = 128 (g,a) rows.
//   x1[k] = relu(u[b,g,k] + w1aT[k][ga])
//   h2    = relu(x1 @ W2 + b2);  out = h2 @ W3 + b3
// W2 (16KB) and w1aT (32KB) live in exactly-48KB static SMEM.
// W2 loads are full-warp broadcasts (LDS.128); w1aT reads are conflict-free
// (lane = ga contiguous, row stride 128 words).
// ---------------------------------------------------------------------------
__global__ void __launch_bounds__(128, 4) mlp_kernel(
    const float* __restrict__ u_unused,  // (g_u used directly)
    const float* __restrict__ w2,        // [64, 64] (k-major rows)
    const float* __restrict__ b2,        // [64]
    const float* __restrict__ w3,        // [64, 1]
    const float* __restrict__ b3,        // [1]
    float* __restrict__ out)             // [B, 8, 16]
{
    __shared__ float sw2[HIDN * 64];     // 16384 B
    __shared__ float sw1a[HIDN * 128];   // 32768 B  (total = 49152 B = 48 KB exactly)

    const int tid = threadIdx.x;
    const int b   = blockIdx.x;

    #pragma unroll
    for (int e = tid; e < HIDN * 64; e += 128) sw2[e] = w2[e];
    #pragma unroll
    for (int e = tid; e < HIDN * 128; e += 128) sw1a[e] = g_w1aT[e];
    __syncthreads();

    const int ga = tid;          // 0..127  (g*16 + a)
    const int g  = ga >> 4;
    const float* __restrict__ ug = g_u + (b * NAG + g) * HIDN;

    float acc[HIDN];
    #pragma unroll
    for (int i = 0; i < HIDN; ++i) acc[i] = __ldg(&b2[i]);

    #pragma unroll 4
    for (int k = 0; k < HIDN; ++k) {
        const float x = __ldg(&ug[k]) + sw1a[k * 128 + ga];
        const float h = fmaxf(x, 0.f);
        const float4* w2r = reinterpret_cast<const float4*>(sw2 + k * 64);
        #pragma unroll
        for (int i = 0; i < 16; ++i) {
            const float4 w = w2r[i];
            acc[4 * i + 0] = fmaf(h, w.x, acc[4 * i + 0]);
            acc[4 * i + 1] = fmaf(h, w.y, acc[4 * i + 1]);
            acc[4 * i + 2] = fmaf(h, w.z, acc[4 * i + 2]);
            acc[4 * i + 3] = fmaf(h, w.w, acc[4 * i + 3]);
        }
    }

    float o = __ldg(&b3[0]);
    #pragma unroll
    for (int k = 0; k < HIDN; ++k)
        o = fmaf(fmaxf(acc[k], 0.f), __ldg(&w3[k]), o);

    out[b * 128 + ga] = o;
}

// ---------------------------------------------------------------------------
extern "C" void kernel_launch(void* const* d_in, const int* in_sizes, int n_in,
                              void* d_out, int out_size) {
    const float* hidden  = (const float*)d_in[0];
    const float* actions = (const float*)d_in[1];
    const float* w1      = (const float*)d_in[2];
    const float* b1      = (const float*)d_in[3];
    const float* w2      = (const float*)d_in[4];
    const float* b2      = (const float*)d_in[5];
    const float* w3      = (const float*)d_in[6];
    const float* b3      = (const float*)d_in[7];
    float* out = (float*)d_out;

    prep_kernel<<<BB / 4, 256>>>(hidden, actions, w1, b1);
    mlp_kernel<<<BB, 128>>>(nullptr, w2, b2, w3, b3, out);
}

// round 2
// speedup vs baseline: 1.1102x; 1.1102x over previous
#include <cuda_runtime.h>

// Problem constants
#define BB   2048
#define NAG  8
#define ACT  16
#define HD   32
#define HIDN 64
// DQ = (HD+ACT)*NAG = 384, per-agent feature stride = 48

// Scratch (__device__ globals: allowed)
__device__ float g_u[BB * NAG * HIDN];        // u[b,g,n] = base(b)+b1 - corr(b,g)  (4 MB)
__device__ float g_w1aT[HIDN * NAG * ACT];    // w1aT[k*128 + ga] = W1[(g*48+32+a)*64 + k]

// ---------------------------------------------------------------------------
// f32x2 packed-FMA helpers (Blackwell sm_103a)
// ---------------------------------------------------------------------------
__device__ __forceinline__ void fma2(unsigned long long& acc,
                                     unsigned long long a,
                                     unsigned long long b) {
    asm("fma.rn.f32x2 %0, %1, %2, %0;" : "+l"(acc) : "l"(a), "l"(b));
}
__device__ __forceinline__ unsigned long long splat2(unsigned int x) {
    unsigned long long r;
    asm("mov.b64 %0, {%1, %1};" : "=l"(r) : "r"(x));
    return r;
}
__device__ __forceinline__ void unpack2(unsigned long long v, float& lo, float& hi) {
    asm("mov.b64 {%0, %1}, %2;" : "=f"(lo), "=f"(hi) : "l"(v));
}

// ---------------------------------------------------------------------------
// Kernel 1: layer-1 factorization (vectorized float4 over output dim).
// Thread = (b, nq): computes base(b)[4n] and per-agent action contributions,
// writes u[b,g,4n] for all 8 agents. CTA 0 also writes transposed W1 action rows.
// ---------------------------------------------------------------------------
__global__ void __launch_bounds__(128) prep_kernel(
    const float* __restrict__ hidden,   // [B, 8, 32]
    const float* __restrict__ actions,  // [B, 8, 16]
    const float* __restrict__ w1,       // [384, 64]
    const float* __restrict__ b1)       // [64]
{
    const int tid = threadIdx.x;
    const int b   = blockIdx.x * 8 + (tid >> 4);
    const int nq  = tid & 15;                       // float4 group (4 outputs)
    const float4* __restrict__ w1v = reinterpret_cast<const float4*>(w1);

    if (blockIdx.x == 0) {
        // g_w1aT[k*128 + ga] = w1[(g*48+32+a)*64 + k]
        for (int e = tid; e < HIDN * 128; e += 128) {
            const int k  = e >> 7;
            const int ga = e & 127;
            const int g  = ga >> 4;
            const int a  = ga & 15;
            g_w1aT[e] = w1[(g * 48 + 32 + a) * 64 + k];
        }
    }

    const float* hb = hidden  + b * (NAG * HD);
    const float* ab = actions + b * (NAG * ACT);

    float4 base = *reinterpret_cast<const float4*>(b1 + nq * 4);

    // Hidden-feature part of base(b)
    #pragma unroll 2
    for (int j = 0; j < NAG; ++j) {
        #pragma unroll
        for (int i = 0; i < HD; ++i) {
            const float  h = __ldg(hb + j * HD + i);
            const float4 w = __ldg(w1v + (j * 48 + i) * 16 + nq);
            base.x = fmaf(h, w.x, base.x);
            base.y = fmaf(h, w.y, base.y);
            base.z = fmaf(h, w.z, base.z);
            base.w = fmaf(h, w.w, base.w);
        }
    }

    // Per-agent true-action contributions
    float4 asum[NAG];
    float4 tot = make_float4(0.f, 0.f, 0.f, 0.f);
    #pragma unroll
    for (int g = 0; g < NAG; ++g) {
        float4 s = make_float4(0.f, 0.f, 0.f, 0.f);
        #pragma unroll
        for (int a = 0; a < ACT; ++a) {
            const float  av = __ldg(ab + g * ACT + a);
            const float4 w  = __ldg(w1v + (g * 48 + 32 + a) * 16 + nq);
            s.x = fmaf(av, w.x, s.x);
            s.y = fmaf(av, w.y, s.y);
            s.z = fmaf(av, w.z, s.z);
            s.w = fmaf(av, w.w, s.w);
        }
        asum[g] = s;
        tot.x += s.x; tot.y += s.y; tot.z += s.z; tot.w += s.w;
    }

    // u[b,g,:] = base + (sum_j act_j) - act_g
    #pragma unroll
    for (int g = 0; g < NAG; ++g) {
        float4 v;
        v.x = base.x + tot.x - asum[g].x;
        v.y = base.y + tot.y - asum[g].y;
        v.z = base.z + tot.z - asum[g].z;
        v.w = base.w + tot.w - asum[g].w;
        *reinterpret_cast<float4*>(&g_u[(b * NAG + g) * HIDN + nq * 4]) = v;
    }
}

// ---------------------------------------------------------------------------
// Kernel 2: fused layers 2+3 with f32x2 packed FMA.
// 1 CTA per batch b, 128 threads.
// Phase 1: sx[k][row] = relu(u[b,g,k] + w1aT[k][row])  (transposed, stride 128)
// Phase 2: thread (ch = tid&1, rp = tid>>1) computes rows {2rp, 2rp+1},
//          cols [ch*32, ch*32+32) with 32 u64 accumulators; per k-step:
//          8 LDS.128 (w2) + 1 LDS.64 (x pair) + 32 fma.rn.f32x2.
// Epilogue: relu + w3 dot, shfl-xor(1) reduce over col halves, float2 store.
// ---------------------------------------------------------------------------
__global__ void __launch_bounds__(128, 4) mlp_kernel(
    const float* __restrict__ w2,        // [64, 64]
    const float* __restrict__ b2,        // [64]
    const float* __restrict__ w3,        // [64]
    const float* __restrict__ b3,        // [1]
    float* __restrict__ out)             // [B, 128]
{
    __shared__ __align__(16) float sw2[HIDN * 64];    // 16 KB
    __shared__ __align__(16) float sx[HIDN * 128];    // 32 KB  (total 48 KB)

    const int tid = threadIdx.x;
    const int b   = blockIdx.x;

    // Load W2 (row-major, [k][c])
    #pragma unroll
    for (int e = tid; e < HIDN * 64; e += 128) sw2[e] = __ldg(w2 + e);

    // Phase 1: build x1 rows (transposed: sx[k*128 + row])
    {
        const int ga = tid;
        const int g  = ga >> 4;
        const float* __restrict__ ug = g_u + (b * NAG + g) * HIDN;
        #pragma unroll 8
        for (int k = 0; k < HIDN; ++k) {
            const float x = __ldg(ug + k) + __ldg(g_w1aT + k * 128 + ga);
            sx[k * 128 + ga] = fmaxf(x, 0.f);
        }
    }
    __syncthreads();

    const int ch = tid & 1;          // column half (32 cols)
    const int rp = tid >> 1;         // row pair index 0..63 -> rows 2rp, 2rp+1
    const int c0 = ch * 32;

    // 32 packed accumulators: acc0 = row 2rp, acc1 = row 2rp+1; pair j = cols c0+2j(+1)
    unsigned long long acc0[16], acc1[16];
    const unsigned long long* __restrict__ b2v =
        reinterpret_cast<const unsigned long long*>(b2 + c0);
    #pragma unroll
    for (int j = 0; j < 16; ++j) {
        const unsigned long long bj = __ldg(b2v + j);
        acc0[j] = bj;
        acc1[j] = bj;
    }

    // Main loop
    #pragma unroll 8
    for (int k = 0; k < HIDN; ++k) {
        const unsigned long long xp =
            *reinterpret_cast<const unsigned long long*>(sx + k * 128 + 2 * rp);
        float xlo, xhi;
        unpack2(xp, xlo, xhi);
        const unsigned long long x0 = splat2(__float_as_uint(xlo));
        const unsigned long long x1 = splat2(__float_as_uint(xhi));

        const float* wrow = sw2 + k * 64 + c0;
        #pragma unroll
        for (int j2 = 0; j2 < 8; ++j2) {
            const ulonglong2 wv = *reinterpret_cast<const ulonglong2*>(wrow + 4 * j2);
            fma2(acc0[2 * j2 + 0], x0, wv.x);
            fma2(acc0[2 * j2 + 1], x0, wv.y);
            fma2(acc1[2 * j2 + 0], x1, wv.x);
            fma2(acc1[2 * j2 + 1], x1, wv.y);
        }
    }

    // Epilogue: relu(h2) . w3
    float o0 = 0.f, o1 = 0.f;
    const float2* __restrict__ w3v = reinterpret_cast<const float2*>(w3 + c0);
    #pragma unroll
    for (int j = 0; j < 16; ++j) {
        const float2 w = __ldg(w3v + j);
        float a, bv;
        unpack2(acc0[j], a, bv);
        o0 = fmaf(fmaxf(a, 0.f), w.x, o0);
        o0 = fmaf(fmaxf(bv, 0.f), w.y, o0);
        unpack2(acc1[j], a, bv);
        o1 = fmaf(fmaxf(a, 0.f), w.x, o1);
        o1 = fmaf(fmaxf(bv, 0.f), w.y, o1);
    }
    o0 += __shfl_xor_sync(0xffffffffu, o0, 1);
    o1 += __shfl_xor_sync(0xffffffffu, o1, 1);

    if (ch == 0) {
        const float bias = __ldg(b3);
        float2 r;
        r.x = o0 + bias;
        r.y = o1 + bias;
        *reinterpret_cast<float2*>(out + b * 128 + 2 * rp) = r;
    }
}

// ---------------------------------------------------------------------------
extern "C" void kernel_launch(void* const* d_in, const int* in_sizes, int n_in,
                              void* d_out, int out_size) {
    const float* hidden  = (const float*)d_in[0];
    const float* actions = (const float*)d_in[1];
    const float* w1      = (const float*)d_in[2];
    const float* b1      = (const float*)d_in[3];
    const float* w2      = (const float*)d_in[4];
    const float* b2      = (const float*)d_in[5];
    const float* w3      = (const float*)d_in[6];
    const float* b3      = (const float*)d_in[7];
    float* out = (float*)d_out;

    prep_kernel<<<BB / 8, 128>>>(hidden, actions, w1, b1);
    mlp_kernel<<<BB, 128>>>(w2, b2, w3, b3, out);
}

// round 4
// speedup vs baseline: 2.3560x; 2.1221x over previous
#include <cuda_runtime.h>
#include <cuda_bf16.h>
#include <cstdint>

// Problem constants
#define BB   2048
#define NAG  8
#define ACT  16
#define HD   32
#define HIDN 64
#define GRID_MMA 444   // 3 CTAs per SM (148 SMs)

// Scratch (__device__ globals: allowed)
__device__ float g_u[BB * NAG * HIDN];        // u[b,g,n] = base(b)+b1 - corr(b,g)  (4 MB)
__device__ float g_w1aT[HIDN * 128];          // w1aT[k*128 + ga] = W1[(g*48+32+a)*64 + k]

// ---------------------------------------------------------------------------
// bf16 split helpers (validated in R2): hi = truncated top 16 bits, lo = rn(residual)
// pack order: (a, b) -> a in low half (memory-first), b in high half.
// ---------------------------------------------------------------------------
__device__ __forceinline__ uint32_t pack_hi(float a, float b) {
    uint32_t r;
    asm("prmt.b32 %0, %1, %2, 0x7632;" : "=r"(r)
        : "r"(__float_as_uint(a)), "r"(__float_as_uint(b)));
    return r;
}
__device__ __forceinline__ uint32_t pack_lo(float a, float b) {
    float ha = __uint_as_float(__float_as_uint(a) & 0xffff0000u);
    float hb = __uint_as_float(__float_as_uint(b) & 0xffff0000u);
    float la = a - ha, lb = b - hb;
    uint32_t r;
    asm("cvt.rn.bf16x2.f32 %0, %1, %2;" : "=r"(r) : "f"(lb), "f"(la));
    return r;
}
__device__ __forceinline__ uint32_t smem_u32(const void* p) {
    uint32_t a;
    asm("{ .reg .u64 t; cvta.to.shared.u64 t, %1; cvt.u32.u64 %0, t; }" : "=r"(a) : "l"(p));
    return a;
}

#define LDSM_X4(r, addr) \
    asm volatile("ldmatrix.sync.aligned.m8n8.x4.shared.b16 {%0,%1,%2,%3}, [%4];" \
        : "=r"((r)[0]), "=r"((r)[1]), "=r"((r)[2]), "=r"((r)[3]) : "r"(addr))
#define LDSM_X4_T(r, addr) \
    asm volatile("ldmatrix.sync.aligned.m8n8.x4.trans.shared.b16 {%0,%1,%2,%3}, [%4];" \
        : "=r"((r)[0]), "=r"((r)[1]), "=r"((r)[2]), "=r"((r)[3]) : "r"(addr))
#define MMA16816(c, a, b0, b1) \
    asm volatile("mma.sync.aligned.m16n8k16.row.col.f32.bf16.bf16.f32 " \
        "{%0,%1,%2,%3}, {%4,%5,%6,%7}, {%8,%9}, {%0,%1,%2,%3};" \
        : "+f"((c)[0]), "+f"((c)[1]), "+f"((c)[2]), "+f"((c)[3]) \
        : "r"((a)[0]), "r"((a)[1]), "r"((a)[2]), "r"((a)[3]), "r"(b0), "r"(b1))

// ---------------------------------------------------------------------------
// Kernel 1: layer-1 factorization (unchanged from R2 — known good)
// ---------------------------------------------------------------------------
__global__ void __launch_bounds__(128) prep_kernel(
    const float* __restrict__ hidden,   // [B, 8, 32]
    const float* __restrict__ actions,  // [B, 8, 16]
    const float* __restrict__ w1,       // [384, 64]
    const float* __restrict__ b1)       // [64]
{
    const int tid = threadIdx.x;
    const int b   = blockIdx.x * 8 + (tid >> 4);
    const int nq  = tid & 15;
    const float4* __restrict__ w1v = reinterpret_cast<const float4*>(w1);

    if (blockIdx.x == 0) {
        for (int e = tid; e < HIDN * 128; e += 128) {
            const int k  = e >> 7;
            const int ga = e & 127;
            const int g  = ga >> 4;
            const int a  = ga & 15;
            g_w1aT[e] = w1[(g * 48 + 32 + a) * 64 + k];
        }
    }

    const float* hb = hidden  + b * (NAG * HD);
    const float* ab = actions + b * (NAG * ACT);

    float4 base = *reinterpret_cast<const float4*>(b1 + nq * 4);

    #pragma unroll 2
    for (int j = 0; j < NAG; ++j) {
        #pragma unroll
        for (int i = 0; i < HD; ++i) {
            const float  h = __ldg(hb + j * HD + i);
            const float4 w = __ldg(w1v + (j * 48 + i) * 16 + nq);
            base.x = fmaf(h, w.x, base.x);
            base.y = fmaf(h, w.y, base.y);
            base.z = fmaf(h, w.z, base.z);
            base.w = fmaf(h, w.w, base.w);
        }
    }

    float4 asum[NAG];
    float4 tot = make_float4(0.f, 0.f, 0.f, 0.f);
    #pragma unroll
    for (int g = 0; g < NAG; ++g) {
        float4 s = make_float4(0.f, 0.f, 0.f, 0.f);
        #pragma unroll
        for (int a = 0; a < ACT; ++a) {
            const float  av = __ldg(ab + g * ACT + a);
            const float4 w  = __ldg(w1v + (g * 48 + 32 + a) * 16 + nq);
            s.x = fmaf(av, w.x, s.x);
            s.y = fmaf(av, w.y, s.y);
            s.z = fmaf(av, w.z, s.z);
            s.w = fmaf(av, w.w, s.w);
        }
        asum[g] = s;
        tot.x += s.x; tot.y += s.y; tot.z += s.z; tot.w += s.w;
    }

    #pragma unroll
    for (int g = 0; g < NAG; ++g) {
        float4 v;
        v.x = base.x + tot.x - asum[g].x;
        v.y = base.y + tot.y - asum[g].y;
        v.z = base.z + tot.z - asum[g].z;
        v.w = base.w + tot.w - asum[g].w;
        *reinterpret_cast<float4*>(&g_u[(b * NAG + g) * HIDN + nq * 4]) = v;
    }
}

// ---------------------------------------------------------------------------
// Kernel 2: persistent mma.sync (HMMA bf16) GEMM + fused layers 2+3.
// Per tile b: D[128,64] = A'[128,192] x B'[192,64] with
//   A' = [x_hi | x_lo | x_hi] (block2 aliases block0 -> only 128 k stored)
//   B' = [W_hi ; W_hi ; W_lo]
// SMEM: A 32KB (128 rows x 16 chunks of 16B, xor-swizzled), B 24KB, b2/w3 512B.
// 4 warps: warp w owns rows [32w, 32w+32) = 2 m-tiles; 8 n-tiles; 12 k-steps.
// ---------------------------------------------------------------------------
#define SM_A   0
#define SM_B   32768
#define SM_B2  57344
#define SM_W3  57600
#define SMEM_SZ 57856

__global__ void __launch_bounds__(128, 3) mma_kernel(
    const float* __restrict__ w2,   // [64, 64] (k-major)
    const float* __restrict__ b2,   // [64]
    const float* __restrict__ w3,   // [64]
    const float* __restrict__ b3,   // [1]
    float* __restrict__ out)        // [B, 128]
{
    extern __shared__ __align__(16) char dsm[];
    const uint32_t smA = smem_u32(dsm) + SM_A;
    const uint32_t smB = smem_u32(dsm) + SM_B;
    float* sb2 = reinterpret_cast<float*>(dsm + SM_B2);
    float* sw3 = reinterpret_cast<float*>(dsm + SM_W3);

    const int tid  = threadIdx.x;
    const int w    = tid >> 5;
    const int lane = tid & 31;

    // ---- stage b2 / w3 ----
    if (tid < 64) {
        sb2[tid] = __ldg(b2 + tid);
        sw3[tid] = __ldg(w3 + tid);
    }
    const float b3v = __ldg(b3);

    // ---- build B' = [W_hi; W_hi; W_lo] (192 rows x 64 n), xor-swizzled ----
    // byte(kk, nc-chunk) = kk*128 + ((nc ^ (kk&7))<<4); word nw in chunk nc=nw>>2.
    for (int e = tid; e < 192 * 32; e += 128) {
        const int kk = e >> 5;
        const int nw = e & 31;
        const int k  = kk & 63;
        const float2 f = __ldg(reinterpret_cast<const float2*>(w2 + k * 64 + 2 * nw));
        const uint32_t word = (kk < 128) ? pack_hi(f.x, f.y) : pack_lo(f.x, f.y);
        const int nc = nw >> 2;
        const uint32_t byte = (uint32_t)kk * 128u + (uint32_t)((nc ^ (kk & 7)) << 4)
                            + (uint32_t)((nw & 3) << 2);
        *reinterpret_cast<uint32_t*>(dsm + SM_B + byte) = word;
    }
    __syncthreads();

    // ---- per-lane ldmatrix address precompute ----
    const int g2    = lane >> 4;          // A: k-chunk half
    const int gh    = (lane >> 3) & 1;    // A: row half / B: k half
    const int lr    = lane & 7;
    const int grp   = lane >> 2;
    const int tig   = lane & 3;

    uint32_t aBase[2];                    // A: warp rows [32w + 16mt + 8gh + lr]
    #pragma unroll
    for (int mt = 0; mt < 2; ++mt)
        aBase[mt] = smA + (uint32_t)(32 * w + 16 * mt + 8 * gh + lr) * 256u;
    // (row & 7) == lr for all mma rows (offsets are multiples of 8)

    const int nadd = lane >> 4;           // B: n-tile half
    const uint32_t bBase = smB + (uint32_t)(8 * ((lane >> 3) & 1) + lr) * 128u;
    uint32_t nxor[4];
    #pragma unroll
    for (int np = 0; np < 4; ++np)
        nxor[np] = (uint32_t)(((2 * np + nadd) ^ lr) << 4);

    const int row_ga = tid;               // build-phase row
    const int gq     = row_ga >> 4;
    const uint32_t rbase = (uint32_t)row_ga * 256u;
    const int rx = row_ga & 7;

    // ---- persistent tile loop ----
    for (int b = blockIdx.x; b < BB; b += GRID_MMA) {
        // build A': x1[row,k] = relu(u[b,g,k] + w1aT[k,row]); hi at chunks 0-7, lo at 8-15
        const float4* up = reinterpret_cast<const float4*>(g_u + (size_t)(b * NAG + gq) * HIDN);
        #pragma unroll
        for (int c8 = 0; c8 < 8; ++c8) {
            const int k0 = c8 * 8;
            const float4 u0 = __ldg(up + c8 * 2);
            const float4 u1 = __ldg(up + c8 * 2 + 1);
            float x[8];
            x[0] = u0.x; x[1] = u0.y; x[2] = u0.z; x[3] = u0.w;
            x[4] = u1.x; x[5] = u1.y; x[6] = u1.z; x[7] = u1.w;
            #pragma unroll
            for (int j = 0; j < 8; ++j)
                x[j] = fmaxf(x[j] + __ldg(g_w1aT + (k0 + j) * 128 + row_ga), 0.f);

            uint4 hi4, lo4;
            hi4.x = pack_hi(x[0], x[1]); hi4.y = pack_hi(x[2], x[3]);
            hi4.z = pack_hi(x[4], x[5]); hi4.w = pack_hi(x[6], x[7]);
            lo4.x = pack_lo(x[0], x[1]); lo4.y = pack_lo(x[2], x[3]);
            lo4.z = pack_lo(x[4], x[5]); lo4.w = pack_lo(x[6], x[7]);

            *reinterpret_cast<uint4*>(dsm + SM_A + rbase + ((c8 ^ rx) << 4))        = hi4;
            *reinterpret_cast<uint4*>(dsm + SM_A + rbase + (((8 + c8) ^ rx) << 4))  = lo4;
        }
        __syncthreads();

        // ---- mma phase: 12 k-steps, 2 m-tiles, 8 n-tiles ----
        float acc[2][8][4];
        #pragma unroll
        for (int mt = 0; mt < 2; ++mt)
            #pragma unroll
            for (int nt = 0; nt < 8; ++nt)
                #pragma unroll
                for (int q = 0; q < 4; ++q) acc[mt][nt][q] = 0.f;

        #pragma unroll
        for (int ks = 0; ks < 12; ++ks) {
            const int aks = (ks < 8) ? ks : ks - 8;      // block2 aliases block0
            uint32_t av[2][4];
            #pragma unroll
            for (int mt = 0; mt < 2; ++mt)
                LDSM_X4(av[mt], aBase[mt] + (uint32_t)(((2 * aks + g2) ^ lr) << 4));

            uint32_t bv[4][4];
            #pragma unroll
            for (int np = 0; np < 4; ++np)
                LDSM_X4_T(bv[np], bBase + (uint32_t)(ks * 2048) + nxor[np]);

            #pragma unroll
            for (int mt = 0; mt < 2; ++mt) {
                #pragma unroll
                for (int np = 0; np < 4; ++np) {
                    MMA16816(acc[mt][2 * np + 0], av[mt], bv[np][0], bv[np][1]);
                    MMA16816(acc[mt][2 * np + 1], av[mt], bv[np][2], bv[np][3]);
                }
            }
        }

        // ---- epilogue: +b2, relu, dot w3, reduce over tig, store ----
        float o[2][2] = {{0.f, 0.f}, {0.f, 0.f}};
        #pragma unroll
        for (int nt = 0; nt < 8; ++nt) {
            const int col = nt * 8 + 2 * tig;
            const float2 bb = *reinterpret_cast<const float2*>(sb2 + col);
            const float2 ww = *reinterpret_cast<const float2*>(sw3 + col);
            #pragma unroll
            for (int mt = 0; mt < 2; ++mt) {
                o[mt][0] = fmaf(fmaxf(acc[mt][nt][0] + bb.x, 0.f), ww.x, o[mt][0]);
                o[mt][0] = fmaf(fmaxf(acc[mt][nt][1] + bb.y, 0.f), ww.y, o[mt][0]);
                o[mt][1] = fmaf(fmaxf(acc[mt][nt][2] + bb.x, 0.f), ww.x, o[mt][1]);
                o[mt][1] = fmaf(fmaxf(acc[mt][nt][3] + bb.y, 0.f), ww.y, o[mt][1]);
            }
        }
        #pragma unroll
        for (int mt = 0; mt < 2; ++mt) {
            #pragma unroll
            for (int rh = 0; rh < 2; ++rh) {
                float v = o[mt][rh];
                v += __shfl_xor_sync(0xffffffffu, v, 1);
                v += __shfl_xor_sync(0xffffffffu, v, 2);
                if (tig == 0) {
                    const int row = 32 * w + 16 * mt + 8 * rh + grp;
                    out[b * 128 + row] = v + b3v;
                }
            }
        }
        __syncthreads();
    }
}

// ---------------------------------------------------------------------------
extern "C" void kernel_launch(void* const* d_in, const int* in_sizes, int n_in,
                              void* d_out, int out_size) {
    const float* hidden  = (const float*)d_in[0];
    const float* actions = (const float*)d_in[1];
    const float* w1      = (const float*)d_in[2];
    const float* b1      = (const float*)d_in[3];
    const float* w2      = (const float*)d_in[4];
    const float* b2      = (const float*)d_in[5];
    const float* w3      = (const float*)d_in[6];
    const float* b3      = (const float*)d_in[7];
    float* out = (float*)d_out;

    cudaFuncSetAttribute(mma_kernel, cudaFuncAttributeMaxDynamicSharedMemorySize, SMEM_SZ);

    prep_kernel<<<BB / 8, 128>>>(hidden, actions, w1, b1);
    mma_kernel<<<GRID_MMA, 128, SMEM_SZ>>>(w2, b2, w3, b3, out);
}